// round 15
// baseline (speedup 1.0000x reference)
#include <cuda_runtime.h>
#include <cuda_fp16.h>

// Shapes (fixed)
#define Bb 8
#define Nn 1024
#define BN 8192
#define Fdim 128
#define Hh 4
#define Kk 32
#define HK 128
#define FOUT 128
#define TP 32            // points per block
#define NBLK (BN/TP)     // 256 blocks -> 2 CTAs/SM

#define KS2 132          // keysT_h row stride in half2 [f2][k]
#define XS2 36           // xT_h row stride in half2 [f2][p]
#define TSs 132          // tS row stride (floats) [p][k]

// smem carve (float slots; each half2 = 1 slot)
#define OFF_X   (64*KS2)             // 8448
#define OFF_TS  (OFF_X + 64*XS2)     // +2304 = 10752
#define OFF_KS  (OFF_TS + TP*TSs)    // +4224 = 14976
#define OFF_XS  (OFF_KS + HK)
#define OFF_CW  (OFF_XS + TP)
#define SMTOT   (OFF_CW + 8)         // 15144 floats ~= 60.6KB

#define OUT_ELEMS (Bb*Kk*FOUT)

__device__ float g_part[NBLK * Kk * Fdim];   // [blk][k][f] partials (4MB)
__device__ float g_linT[Fdim * FOUT];        // [f][fo]

// ---------------------------------------------------------------------------
// distS: L1 dist via half2 min-sum + student-t + head-normalize + conv +
// softmax + partial pooling. 256 blocks x 512 threads, ~61KB smem,
// 2 CTAs/SM (32 warps) for latency hiding + tail overlap.
// ---------------------------------------------------------------------------
__global__ __launch_bounds__(512, 2) void distS_kernel(
    const float* __restrict__ x, const float* __restrict__ keys,
    const float* __restrict__ convw, const float* __restrict__ linw,
    float* __restrict__ Sg)
{
    extern __shared__ float sm[];
    __half2* keysT_h = (__half2*)sm;            // [64][KS2]
    __half2* xT_h    = (__half2*)(sm + OFF_X);  // [64][XS2]
    float* tS   = sm + OFF_TS;                  // [TP][TSs]
    float* ksum = sm + OFF_KS;                  // [128]
    float* xsum = sm + OFF_XS;                  // [32]
    float* cw   = sm + OFF_CW;                  // [8]
    float* redK = tS;                           // [4][128] (aliased, pre-tS)
    float* redX = tS + 512;                     // [16][32]

    const int tid = threadIdx.x;
    const int bid = blockIdx.x;
    const int p0  = bid * TP;

    if (tid < Hh) cw[tid] = convw[tid];
    // side-write transposed lin_w (first 128 blocks, one row each)
    if (bid < FOUT && tid < Fdim)
        g_linT[tid * FOUT + bid] = linw[bid * Fdim + tid];

    // ---- keys: global float4 -> transposed half2 smem [f2][k] ----
    {
        const float4* kg4 = (const float4*)keys;
        #pragma unroll
        for (int it = 0; it < 8; it++) {
            int i4 = tid + it * 512;            // 4096 float4
            int k  = i4 >> 5;
            int f4 = i4 & 31;
            float4 v = kg4[i4];
            keysT_h[(f4 * 2 + 0) * KS2 + k] = __floats2half2_rn(v.x, v.y);
            keysT_h[(f4 * 2 + 1) * KS2 + k] = __floats2half2_rn(v.z, v.w);
        }
    }
    // ---- x tile: global float4 -> transposed half2 smem [f2][p] ----
    {
        const float4* xg4 = (const float4*)(x + (size_t)p0 * Fdim);
        #pragma unroll
        for (int it = 0; it < 2; it++) {
            int i4 = tid + it * 512;            // 1024 float4
            int p  = i4 >> 5;
            int f4 = i4 & 31;
            float4 v = xg4[i4];
            xT_h[(f4 * 2 + 0) * XS2 + p] = __floats2half2_rn(v.x, v.y);
            xT_h[(f4 * 2 + 1) * XS2 + p] = __floats2half2_rn(v.z, v.w);
        }
    }
    __syncthreads();

    // ---- row sums in fp32 FROM the h2-rounded values (consistency!) ----
    {
        int k = tid & 127, part = tid >> 7;     // 4 parts x 16 f2
        float s = 0.f;
        #pragma unroll
        for (int i = 0; i < 16; i++) {
            __half2 h = keysT_h[(part * 16 + i) * KS2 + k];
            s += __low2float(h) + __high2float(h);
        }
        redK[part * HK + k] = s;
    }
    __syncthreads();
    {
        int p = tid & 31, part = tid >> 5;      // 16 parts x 4 f2
        float s = 0.f;
        #pragma unroll
        for (int i = 0; i < 4; i++) {
            __half2 h = xT_h[(part * 4 + i) * XS2 + p];
            s += __low2float(h) + __high2float(h);
        }
        redX[part * TP + p] = s;
    }
    __syncthreads();
    if (tid < HK) {
        float s = 0.f;
        #pragma unroll
        for (int r = 0; r < 4; r++) s += redK[r * HK + tid];
        ksum[tid] = s;
    } else if (tid < HK + TP) {
        int p = tid - HK;
        float s = 0.f;
        #pragma unroll
        for (int r = 0; r < 16; r++) s += redX[r * TP + p];
        xsum[p] = s;
    }
    __syncthreads();

    // ---- half2 min-sum main loop: 4 keys x 2 points, 2 f per instr ----
    const int kg = tid & 31;    // keys  [kg*4, kg*4+4)
    const int pg = tid >> 5;    // points[pg*2, pg*2+2)  (warp-uniform)
    const float4* kp4 = (const float4*)(keysT_h + kg * 4);  // 33 f4 per f2
    const float2* xp2 = (const float2*)(xT_h + pg * 2);     // 18 f2 per f2

    float fa[4][2];
    #pragma unroll
    for (int i = 0; i < 4; i++) { fa[i][0] = 0.f; fa[i][1] = 0.f; }

    #pragma unroll
    for (int c = 0; c < 8; c++) {               // 8 chunks of 8 f2 (16 f)
        __half2 acc[4][2];
        #pragma unroll
        for (int i = 0; i < 4; i++) {
            acc[i][0] = __floats2half2_rn(0.f, 0.f);
            acc[i][1] = __floats2half2_rn(0.f, 0.f);
        }
        #pragma unroll
        for (int u = 0; u < 8; u++) {
            int f2 = c * 8 + u;
            float4 kr = kp4[f2 * 33];           // 4 keys' half2 (cf 4-phase)
            float2 xr = xp2[f2 * 18];           // 2 points' half2 (broadcast)
            __half2 kh[4] = {*(__half2*)&kr.x, *(__half2*)&kr.y,
                             *(__half2*)&kr.z, *(__half2*)&kr.w};
            __half2 xh[2] = {*(__half2*)&xr.x, *(__half2*)&xr.y};
            #pragma unroll
            for (int i = 0; i < 4; i++) {
                acc[i][0] = __hadd2(acc[i][0], __hmin2(kh[i], xh[0]));
                acc[i][1] = __hadd2(acc[i][1], __hmin2(kh[i], xh[1]));
            }
        }
        #pragma unroll
        for (int i = 0; i < 4; i++) {
            fa[i][0] += __low2float(acc[i][0]) + __high2float(acc[i][0]);
            fa[i][1] += __low2float(acc[i][1]) + __high2float(acc[i][1]);
        }
    }

    // ---- student-t (TAU=1): t = 1/(1+d^2) into tS[p][k] ----
    {
        float4 kv = *(const float4*)(ksum + kg * 4);
        float kf[4] = {kv.x, kv.y, kv.z, kv.w};
        #pragma unroll
        for (int j = 0; j < 2; j++) {
            int p = pg * 2 + j;
            float xs_ = xsum[p];
            float4 tv;
            float d;
            d = kf[0] + xs_ - 2.f * fa[0][j]; tv.x = __fdividef(1.f, fmaf(d, d, 1.f));
            d = kf[1] + xs_ - 2.f * fa[1][j]; tv.y = __fdividef(1.f, fmaf(d, d, 1.f));
            d = kf[2] + xs_ - 2.f * fa[2][j]; tv.z = __fdividef(1.f, fmaf(d, d, 1.f));
            d = kf[3] + xs_ - 2.f * fa[3][j]; tv.w = __fdividef(1.f, fmaf(d, d, 1.f));
            *(float4*)(tS + p * TSs + kg * 4) = tv;
        }
    }
    __syncthreads();

    // ---- per-point: head-normalize + conv + softmax (8 lanes / point) ----
    if (tid < TP * 8) {
        int p = tid >> 3;          // 32 points x 8 lanes = 256 threads
        int l = tid & 7;
        float* row = tS + p * TSs;
        float4 t0 = *(float4*)(row +  0 + l * 4);
        float4 t1 = *(float4*)(row + 32 + l * 4);
        float4 t2 = *(float4*)(row + 64 + l * 4);
        float4 t3 = *(float4*)(row + 96 + l * 4);

        float h0 = t0.x + t0.y + t0.z + t0.w;
        float h1 = t1.x + t1.y + t1.z + t1.w;
        float h2 = t2.x + t2.y + t2.z + t2.w;
        float h3 = t3.x + t3.y + t3.z + t3.w;
        #pragma unroll
        for (int m = 1; m < 8; m <<= 1) {
            h0 += __shfl_xor_sync(0xffffffffu, h0, m);
            h1 += __shfl_xor_sync(0xffffffffu, h1, m);
            h2 += __shfl_xor_sync(0xffffffffu, h2, m);
            h3 += __shfl_xor_sync(0xffffffffu, h3, m);
        }
        float w0 = __fdividef(cw[0], h0);
        float w1 = __fdividef(cw[1], h1);
        float w2 = __fdividef(cw[2], h2);
        float w3 = __fdividef(cw[3], h3);

        float C0 = t0.x * w0 + t1.x * w1 + t2.x * w2 + t3.x * w3;
        float C1 = t0.y * w0 + t1.y * w1 + t2.y * w2 + t3.y * w3;
        float C2 = t0.z * w0 + t1.z * w1 + t2.z * w2 + t3.z * w3;
        float C3 = t0.w * w0 + t1.w * w1 + t2.w * w2 + t3.w * w3;

        float mx = fmaxf(fmaxf(C0, C1), fmaxf(C2, C3));
        #pragma unroll
        for (int m = 1; m < 8; m <<= 1)
            mx = fmaxf(mx, __shfl_xor_sync(0xffffffffu, mx, m));

        float e0 = __expf(C0 - mx), e1 = __expf(C1 - mx);
        float e2 = __expf(C2 - mx), e3 = __expf(C3 - mx);
        float s = e0 + e1 + e2 + e3;
        #pragma unroll
        for (int m = 1; m < 8; m <<= 1)
            s += __shfl_xor_sync(0xffffffffu, s, m);
        float inv = __fdividef(1.f, s);

        float4 Sv = make_float4(e0 * inv, e1 * inv, e2 * inv, e3 * inv);
        *(float4*)(row + l * 4) = Sv;
        *(float4*)(Sg + (size_t)(p0 + p) * Kk + l * 4) = Sv;
    }
    __syncthreads();

    // ---- partial pooling: g_part[bid][k][f] = sum_p S[p][k] * x[p][f] ----
    {
        int k  = tid >> 4;          // 32 k (2 distinct per warp -> broadcast)
        int f4 = tid & 15;          // f chunks f4 and f4+16
        const float4* xg = (const float4*)(x + (size_t)p0 * Fdim);
        float4 A = make_float4(0.f, 0.f, 0.f, 0.f);
        float4 B = make_float4(0.f, 0.f, 0.f, 0.f);
        #pragma unroll 4
        for (int n = 0; n < TP; n++) {
            float sv  = tS[n * TSs + k];
            float4 v0 = xg[n * 32 + f4];
            float4 v1 = xg[n * 32 + f4 + 16];
            A.x = fmaf(sv, v0.x, A.x); A.y = fmaf(sv, v0.y, A.y);
            A.z = fmaf(sv, v0.z, A.z); A.w = fmaf(sv, v0.w, A.w);
            B.x = fmaf(sv, v1.x, B.x); B.y = fmaf(sv, v1.y, B.y);
            B.z = fmaf(sv, v1.z, B.z); B.w = fmaf(sv, v1.w, B.w);
        }
        float* dst = &g_part[((size_t)bid * Kk + k) * Fdim];
        *(float4*)(dst + f4 * 4)        = A;
        *(float4*)(dst + (f4 + 16) * 4) = B;
    }
}

// ---------------------------------------------------------------------------
// out: single latency epoch. 256 blocks x 512 threads. All 40 global loads
// per thread (8 partials + 32 GEMV weights) issue before the first barrier.
// ---------------------------------------------------------------------------
__global__ __launch_bounds__(512) void out_kernel(float* __restrict__ out)
{
    const int row = blockIdx.x;           // b*32 + k
    const int b   = row >> 5;
    const int k   = row & 31;
    const int tid = threadIdx.x;
    __shared__ float red[4 * Fdim];
    __shared__ float pr[Fdim];

    const int c4 = tid >> 7;              // 0..3 (stage-1 chunk group of 8)
    const int f  = tid & 127;             // stage-1 feature
    const int fo = tid & 127;             // GEMV output feature
    const int q  = tid >> 7;              // GEMV f-quarter

    // phase A: all independent global loads up front (MLP ~40)
    float s[8];
    {
        const float* gp =
            &g_part[(((size_t)(b * 32 + c4 * 8)) * Kk + k) * Fdim + f];
        #pragma unroll
        for (int i = 0; i < 8; i++)
            s[i] = gp[(size_t)i * Kk * Fdim];
    }
    float w[32];
    #pragma unroll
    for (int i = 0; i < 32; i++)
        w[i] = g_linT[(q * 32 + i) * FOUT + fo];   // coalesced

    red[c4 * Fdim + f] = ((s[0] + s[1]) + (s[2] + s[3]))
                       + ((s[4] + s[5]) + (s[6] + s[7]));
    __syncthreads();
    if (tid < Fdim)
        pr[tid] = red[tid] + red[Fdim + tid] + red[2 * Fdim + tid]
                + red[3 * Fdim + tid];
    __syncthreads();

    // GEMV: weights already in registers, pr broadcast from smem
    float a = 0.f;
    #pragma unroll
    for (int i = 0; i < 32; i++)
        a = fmaf(pr[q * 32 + i], w[i], a);
    red[q * Fdim + fo] = a;
    __syncthreads();
    if (tid < Fdim) {
        float v = red[tid] + red[Fdim + tid] + red[2 * Fdim + tid]
                + red[3 * Fdim + tid];
        out[(size_t)row * FOUT + tid] = (v >= 0.f) ? v : 0.01f * v;
    }
}

// ---------------------------------------------------------------------------
extern "C" void kernel_launch(void* const* d_in, const int* in_sizes, int n_in,
                              void* d_out, int out_size)
{
    const float* x     = (const float*)d_in[0];
    const float* keys  = (const float*)d_in[1];
    const float* convw = (const float*)d_in[2];
    const float* linw  = (const float*)d_in[3];
    float* out = (float*)d_out;                   // [8,32,128]
    float* Sg  = out + OUT_ELEMS;                 // [8192,32]

    const int smemA = SMTOT * (int)sizeof(float);
    cudaFuncSetAttribute(distS_kernel,
                         cudaFuncAttributeMaxDynamicSharedMemorySize, smemA);

    distS_kernel<<<NBLK, 512, smemA>>>(x, keys, convw, linw, Sg);
    out_kernel<<<Bb * Kk, 512>>>(out);
}

// round 16
// speedup vs baseline: 1.0779x; 1.0779x over previous
#include <cuda_runtime.h>
#include <cuda_fp16.h>

// Shapes (fixed)
#define Bb 8
#define Nn 1024
#define BN 8192
#define Fdim 128
#define Hh 4
#define Kk 32
#define HK 128
#define FOUT 128
#define TP 64            // points per block
#define NBLK (BN/TP)     // 128 blocks

#define KS2 132          // keysT_h row stride in half2 [f2][k]
#define XS2 68           // xT_h row stride in half2 [f2][p]
#define TSs 132          // tS row stride (floats) [p][k]

// smem carve (float slots; each half2 = 1 slot)
#define OFF_X   (64*KS2)             // 8448
#define OFF_TS  (OFF_X + 64*XS2)     // +4352
#define OFF_KS  (OFF_TS + TP*TSs)    // +8448
#define OFF_XS  (OFF_KS + HK)
#define OFF_CW  (OFF_XS + TP)
#define SMTOT   (OFF_CW + 8)         // 21456 floats ~= 86KB

#define OUT_ELEMS (Bb*Kk*FOUT)

__device__ float g_part[NBLK * Kk * Fdim];   // [blk][k][f] partials (2MB)
__device__ float g_linT[Fdim * FOUT];        // [f][fo]

// ---------------------------------------------------------------------------
// distS: L1 dist via half2 min-sum + student-t + head-normalize + conv +
// softmax + partial pooling. 128 blocks x 512 threads, ~86KB smem.
// Rowsums fused into the convert loops via warp shfl (one k/p per warp-iter).
// ---------------------------------------------------------------------------
__global__ __launch_bounds__(512, 1) void distS_kernel(
    const float* __restrict__ x, const float* __restrict__ keys,
    const float* __restrict__ convw, const float* __restrict__ linw,
    float* __restrict__ Sg)
{
    extern __shared__ float sm[];
    __half2* keysT_h = (__half2*)sm;            // [64][KS2]
    __half2* xT_h    = (__half2*)(sm + OFF_X);  // [64][XS2]
    float* tS   = sm + OFF_TS;                  // [TP][TSs]
    float* ksum = sm + OFF_KS;                  // [128]
    float* xsum = sm + OFF_XS;                  // [64]
    float* cw   = sm + OFF_CW;                  // [8]

    const int tid = threadIdx.x;
    const int bid = blockIdx.x;
    const int p0  = bid * TP;

    if (tid < Hh) cw[tid] = convw[tid];
    // side-write transposed lin_w (each of 128 blocks does one row)
    if (tid < Fdim)
        g_linT[tid * FOUT + bid] = linw[bid * Fdim + tid];

    // ---- keys: float4 -> transposed half2 smem [f2][k], ksum fused ----
    // warp lanes cover f4=0..31 (all 128 f) for ONE k -> shfl-reduce = ksum[k]
    {
        const float4* kg4 = (const float4*)keys;
        #pragma unroll
        for (int it = 0; it < 8; it++) {
            int i4 = tid + it * 512;            // 4096 float4
            int k  = i4 >> 5;                   // warp-uniform
            int f4 = i4 & 31;
            float4 v = kg4[i4];
            __half2 h0 = __floats2half2_rn(v.x, v.y);
            __half2 h1 = __floats2half2_rn(v.z, v.w);
            keysT_h[(f4 * 2 + 0) * KS2 + k] = h0;
            keysT_h[(f4 * 2 + 1) * KS2 + k] = h1;
            float s = (__low2float(h0) + __high2float(h0))
                    + (__low2float(h1) + __high2float(h1));
            #pragma unroll
            for (int m = 1; m < 32; m <<= 1)
                s += __shfl_xor_sync(0xffffffffu, s, m);
            if ((tid & 31) == 0) ksum[k] = s;
        }
    }
    // ---- x tile: float4 -> transposed half2 smem [f2][p], xsum fused ----
    {
        const float4* xg4 = (const float4*)(x + (size_t)p0 * Fdim);
        #pragma unroll
        for (int it = 0; it < 4; it++) {
            int i4 = tid + it * 512;            // 2048 float4
            int p  = i4 >> 5;                   // warp-uniform
            int f4 = i4 & 31;
            float4 v = xg4[i4];
            __half2 h0 = __floats2half2_rn(v.x, v.y);
            __half2 h1 = __floats2half2_rn(v.z, v.w);
            xT_h[(f4 * 2 + 0) * XS2 + p] = h0;
            xT_h[(f4 * 2 + 1) * XS2 + p] = h1;
            float s = (__low2float(h0) + __high2float(h0))
                    + (__low2float(h1) + __high2float(h1));
            #pragma unroll
            for (int m = 1; m < 32; m <<= 1)
                s += __shfl_xor_sync(0xffffffffu, s, m);
            if ((tid & 31) == 0) xsum[p] = s;
        }
    }
    __syncthreads();

    // ---- half2 min-sum main loop: 4 keys x 4 points, 2 f per instr ----
    const int kg = tid & 31;    // keys  [kg*4, kg*4+4)
    const int pg = tid >> 5;    // points[pg*4, pg*4+4)  (warp-uniform)
    const float4* kp4 = (const float4*)(keysT_h + kg * 4);  // stride 33 f4/f2
    const float4* xp4 = (const float4*)(xT_h + pg * 4);     // stride 17 f4/f2

    float fa[4][4];
    #pragma unroll
    for (int i = 0; i < 4; i++)
        #pragma unroll
        for (int j = 0; j < 4; j++) fa[i][j] = 0.f;

    #pragma unroll
    for (int c = 0; c < 8; c++) {               // 8 chunks of 8 f2 (16 f)
        __half2 acc[4][4];
        #pragma unroll
        for (int i = 0; i < 4; i++)
            #pragma unroll
            for (int j = 0; j < 4; j++)
                acc[i][j] = __floats2half2_rn(0.f, 0.f);

        #pragma unroll
        for (int u = 0; u < 8; u++) {
            int f2 = c * 8 + u;
            float4 kr = kp4[f2 * 33];           // 4 keys' half2  (cf 4-phase)
            float4 xr = xp4[f2 * 17];           // 4 points' half2 (broadcast)
            __half2 kh[4] = {*(__half2*)&kr.x, *(__half2*)&kr.y,
                             *(__half2*)&kr.z, *(__half2*)&kr.w};
            __half2 xh[4] = {*(__half2*)&xr.x, *(__half2*)&xr.y,
                             *(__half2*)&xr.z, *(__half2*)&xr.w};
            #pragma unroll
            for (int i = 0; i < 4; i++)
                #pragma unroll
                for (int j = 0; j < 4; j++)
                    acc[i][j] = __hadd2(acc[i][j], __hmin2(kh[i], xh[j]));
        }
        // drain chunk to fp32
        #pragma unroll
        for (int i = 0; i < 4; i++)
            #pragma unroll
            for (int j = 0; j < 4; j++)
                fa[i][j] += __low2float(acc[i][j]) + __high2float(acc[i][j]);
    }

    // ---- student-t (TAU=1): t = 1/(1+d^2) into tS[p][k] ----
    {
        float4 kv = *(const float4*)(ksum + kg * 4);
        float kf[4] = {kv.x, kv.y, kv.z, kv.w};
        #pragma unroll
        for (int j = 0; j < 4; j++) {
            int p = pg * 4 + j;
            float xs_ = xsum[p];
            float4 tv;
            float d;
            d = kf[0] + xs_ - 2.f * fa[0][j]; tv.x = __fdividef(1.f, fmaf(d, d, 1.f));
            d = kf[1] + xs_ - 2.f * fa[1][j]; tv.y = __fdividef(1.f, fmaf(d, d, 1.f));
            d = kf[2] + xs_ - 2.f * fa[2][j]; tv.z = __fdividef(1.f, fmaf(d, d, 1.f));
            d = kf[3] + xs_ - 2.f * fa[3][j]; tv.w = __fdividef(1.f, fmaf(d, d, 1.f));
            *(float4*)(tS + p * TSs + kg * 4) = tv;
        }
    }
    __syncthreads();

    // ---- per-point: head-normalize + conv + softmax (8 lanes / point) ----
    {
        int p = tid >> 3;          // 64 points x 8 lanes = 512
        int l = tid & 7;
        float* row = tS + p * TSs;
        float4 t0 = *(float4*)(row +  0 + l * 4);
        float4 t1 = *(float4*)(row + 32 + l * 4);
        float4 t2 = *(float4*)(row + 64 + l * 4);
        float4 t3 = *(float4*)(row + 96 + l * 4);

        float h0 = t0.x + t0.y + t0.z + t0.w;
        float h1 = t1.x + t1.y + t1.z + t1.w;
        float h2 = t2.x + t2.y + t2.z + t2.w;
        float h3 = t3.x + t3.y + t3.z + t3.w;
        #pragma unroll
        for (int m = 1; m < 8; m <<= 1) {
            h0 += __shfl_xor_sync(0xffffffffu, h0, m);
            h1 += __shfl_xor_sync(0xffffffffu, h1, m);
            h2 += __shfl_xor_sync(0xffffffffu, h2, m);
            h3 += __shfl_xor_sync(0xffffffffu, h3, m);
        }
        float w0 = __fdividef(cw[0], h0);
        float w1 = __fdividef(cw[1], h1);
        float w2 = __fdividef(cw[2], h2);
        float w3 = __fdividef(cw[3], h3);

        float C0 = t0.x * w0 + t1.x * w1 + t2.x * w2 + t3.x * w3;
        float C1 = t0.y * w0 + t1.y * w1 + t2.y * w2 + t3.y * w3;
        float C2 = t0.z * w0 + t1.z * w1 + t2.z * w2 + t3.z * w3;
        float C3 = t0.w * w0 + t1.w * w1 + t2.w * w2 + t3.w * w3;

        float mx = fmaxf(fmaxf(C0, C1), fmaxf(C2, C3));
        #pragma unroll
        for (int m = 1; m < 8; m <<= 1)
            mx = fmaxf(mx, __shfl_xor_sync(0xffffffffu, mx, m));

        float e0 = __expf(C0 - mx), e1 = __expf(C1 - mx);
        float e2 = __expf(C2 - mx), e3 = __expf(C3 - mx);
        float s = e0 + e1 + e2 + e3;
        #pragma unroll
        for (int m = 1; m < 8; m <<= 1)
            s += __shfl_xor_sync(0xffffffffu, s, m);
        float inv = __fdividef(1.f, s);

        float4 Sv = make_float4(e0 * inv, e1 * inv, e2 * inv, e3 * inv);
        *(float4*)(row + l * 4) = Sv;
        *(float4*)(Sg + (size_t)(p0 + p) * Kk + l * 4) = Sv;
    }
    __syncthreads();

    // ---- partial pooling: g_part[bid][k][f] = sum_p S[p][k] * x[p][f] ----
    {
        int k  = tid >> 4;          // 32 k (2 distinct per warp -> broadcast)
        int f4 = tid & 15;          // f chunks f4 and f4+16
        const float4* xg = (const float4*)(x + (size_t)p0 * Fdim);
        float4 A = make_float4(0.f, 0.f, 0.f, 0.f);
        float4 B = make_float4(0.f, 0.f, 0.f, 0.f);
        #pragma unroll 4
        for (int n = 0; n < TP; n++) {
            float sv  = tS[n * TSs + k];
            float4 v0 = xg[n * 32 + f4];
            float4 v1 = xg[n * 32 + f4 + 16];
            A.x = fmaf(sv, v0.x, A.x); A.y = fmaf(sv, v0.y, A.y);
            A.z = fmaf(sv, v0.z, A.z); A.w = fmaf(sv, v0.w, A.w);
            B.x = fmaf(sv, v1.x, B.x); B.y = fmaf(sv, v1.y, B.y);
            B.z = fmaf(sv, v1.z, B.z); B.w = fmaf(sv, v1.w, B.w);
        }
        float* dst = &g_part[((size_t)bid * Kk + k) * Fdim];
        *(float4*)(dst + f4 * 4)        = A;
        *(float4*)(dst + (f4 + 16) * 4) = B;
    }
}

// ---------------------------------------------------------------------------
// out: single latency epoch. 256 blocks x 512 threads. All 36 global loads
// per thread (4 partials + 32 GEMV weights) issue before the first barrier.
// ---------------------------------------------------------------------------
__global__ __launch_bounds__(512) void out_kernel(float* __restrict__ out)
{
    const int row = blockIdx.x;           // b*32 + k
    const int b   = row >> 5;
    const int k   = row & 31;
    const int tid = threadIdx.x;
    __shared__ float red[4 * Fdim];
    __shared__ float pr[Fdim];

    const int c4 = tid >> 7;              // 0..3 (stage-1 chunk group)
    const int f  = tid & 127;             // stage-1 feature
    const int fo = tid & 127;             // GEMV output feature
    const int q  = tid >> 7;              // GEMV f-quarter

    // phase A: all independent global loads up front (MLP ~36)
    float s0, s1, s2, s3;
    {
        const float* gp =
            &g_part[(((size_t)(b * 16 + c4 * 4)) * Kk + k) * Fdim + f];
        s0 = gp[0];
        s1 = gp[(size_t)Kk * Fdim];
        s2 = gp[(size_t)2 * Kk * Fdim];
        s3 = gp[(size_t)3 * Kk * Fdim];
    }
    float w[32];
    #pragma unroll
    for (int i = 0; i < 32; i++)
        w[i] = g_linT[(q * 32 + i) * FOUT + fo];   // coalesced

    red[c4 * Fdim + f] = (s0 + s1) + (s2 + s3);
    __syncthreads();
    if (tid < Fdim)
        pr[tid] = red[tid] + red[Fdim + tid] + red[2 * Fdim + tid]
                + red[3 * Fdim + tid];
    __syncthreads();

    // GEMV: weights already in registers, pr broadcast from smem
    float a = 0.f;
    #pragma unroll
    for (int i = 0; i < 32; i++)
        a = fmaf(pr[q * 32 + i], w[i], a);
    red[q * Fdim + fo] = a;
    __syncthreads();
    if (tid < Fdim) {
        float v = red[tid] + red[Fdim + tid] + red[2 * Fdim + tid]
                + red[3 * Fdim + tid];
        out[(size_t)row * FOUT + tid] = (v >= 0.f) ? v : 0.01f * v;
    }
}

// ---------------------------------------------------------------------------
extern "C" void kernel_launch(void* const* d_in, const int* in_sizes, int n_in,
                              void* d_out, int out_size)
{
    const float* x     = (const float*)d_in[0];
    const float* keys  = (const float*)d_in[1];
    const float* convw = (const float*)d_in[2];
    const float* linw  = (const float*)d_in[3];
    float* out = (float*)d_out;                   // [8,32,128]
    float* Sg  = out + OUT_ELEMS;                 // [8192,32]

    const int smemA = SMTOT * (int)sizeof(float);
    cudaFuncSetAttribute(distS_kernel,
                         cudaFuncAttributeMaxDynamicSharedMemorySize, smemA);

    distS_kernel<<<NBLK, 512, smemA>>>(x, keys, convw, linw, Sg);
    out_kernel<<<Bb * Kk, 512>>>(out);
}